// round 14
// baseline (speedup 1.0000x reference)
#include <cuda_runtime.h>
#include <cuda_bf16.h>
#include <cuda_fp16.h>
#include <math.h>
#include <stdint.h>

#define N_NODES 50000
#define N_EDGES 800000
#define DH 128
#define DOUT 64
#define XN (N_NODES * DH)
#define SCAN_BLOCKS 196   // 196*256 = 50176 >= N_NODES

// ---------------- scratch (device globals) ----------------
__device__ __nv_bfloat16 g_xh[XN], g_xl[XN];
__device__ __nv_bfloat16 g_m1h[XN], g_m1l[XN];
__device__ __nv_bfloat16 g_m2h[XN], g_m2l[XN];
__device__ float g_q1[N_NODES * DH];
__device__ __half g_p1h[N_NODES * DH];     // fp16 p1 (score + aggregation)
__device__ float g_q2[N_NODES * DOUT];
__device__ float g_p2[N_NODES * DOUT];
__device__ int   g_cnt[N_NODES];
__device__ int   g_fill[N_NODES];
__device__ int   g_rowptr[N_NODES + 1];
__device__ int   g_csrc[N_EDGES];
__device__ int   g_part[SCAN_BLOCKS];
__device__ int   g_partoff[SCAN_BLOCKS];

__device__ __nv_bfloat16 g_w0h[128 * 128], g_w0l[128 * 128];
__device__ __nv_bfloat16 g_wq1h[128 * 128], g_wq1l[128 * 128];
__device__ __nv_bfloat16 g_wp1h[128 * 128], g_wp1l[128 * 128];
__device__ __nv_bfloat16 g_wq2h[128 * 64], g_wq2l[128 * 64];
__device__ __nv_bfloat16 g_wp2h[128 * 64], g_wp2l[128 * 64];

// ---------------- helpers ----------------
__device__ __forceinline__ float gelu_erf(float x) {
    return 0.5f * x * (1.0f + erff(x * 0.70710678118654752440f));
}

__device__ __forceinline__ uint32_t smem_u32(const void* p) {
    uint32_t a;
    asm("{ .reg .u64 t; cvta.to.shared.u64 t, %1; cvt.u32.u64 %0, t; }" : "=r"(a) : "l"(p));
    return a;
}

__device__ __forceinline__ void ldx4(uint32_t* r, uint32_t addr) {
    asm volatile("ldmatrix.sync.aligned.m8n8.x4.shared.b16 {%0,%1,%2,%3}, [%4];"
                 : "=r"(r[0]), "=r"(r[1]), "=r"(r[2]), "=r"(r[3]) : "r"(addr));
}

__device__ __forceinline__ void ldx4t(uint32_t* r, uint32_t addr) {
    asm volatile("ldmatrix.sync.aligned.m8n8.x4.trans.shared.b16 {%0,%1,%2,%3}, [%4];"
                 : "=r"(r[0]), "=r"(r[1]), "=r"(r[2]), "=r"(r[3]) : "r"(addr));
}

__device__ __forceinline__ void mma16816(float* c, const uint32_t* a, uint32_t b0, uint32_t b1) {
    asm volatile(
        "mma.sync.aligned.m16n8k16.row.col.f32.bf16.bf16.f32 "
        "{%0,%1,%2,%3}, {%4,%5,%6,%7}, {%8,%9}, {%0,%1,%2,%3};"
        : "+f"(c[0]), "+f"(c[1]), "+f"(c[2]), "+f"(c[3])
        : "r"(a[0]), "r"(a[1]), "r"(a[2]), "r"(a[3]), "r"(b0), "r"(b1));
}

__device__ __forceinline__ void split2(float a, float b, uint32_t& hi, uint32_t& lo) {
    __nv_bfloat16 ha = __float2bfloat16(a), hb = __float2bfloat16(b);
    __nv_bfloat16 la = __float2bfloat16(a - __bfloat162float(ha));
    __nv_bfloat16 lb = __float2bfloat16(b - __bfloat162float(hb));
    hi = (uint32_t)__bfloat16_as_ushort(ha) | ((uint32_t)__bfloat16_as_ushort(hb) << 16);
    lo = (uint32_t)__bfloat16_as_ushort(la) | ((uint32_t)__bfloat16_as_ushort(lb) << 16);
}

// load one 8-half slice of a p1 row (16B) and expand to two float4
__device__ __forceinline__ void ld_p16(const uint4* p16, int row, int hl,
                                       float4& v0, float4& v1) {
    uint4 r = p16[(size_t)row * 16 + hl];
    float2 f0 = __half22float2(*(__half2*)&r.x);
    float2 f1 = __half22float2(*(__half2*)&r.y);
    float2 f2 = __half22float2(*(__half2*)&r.z);
    float2 f3 = __half22float2(*(__half2*)&r.w);
    v0 = make_float4(f0.x, f0.y, f1.x, f1.y);
    v1 = make_float4(f2.x, f2.y, f3.x, f3.y);
}

#define LRELU(d) ((d) > 0.f ? (d) : 0.2f * (d))

// ---------------- merged prep (float4 vectorized) ----------------
__global__ void k_prep_all(const float4* __restrict__ x,
                           const float4* __restrict__ W0, const float4* __restrict__ Wq1,
                           const float4* __restrict__ Wp1, const float4* __restrict__ Wq2,
                           const float4* __restrict__ Wp2) {
    int idx = blockIdx.x * blockDim.x + threadIdx.x;
    const float4* srcp;
    __nv_bfloat16 *dh, *dl;
    int off;
    const int X4 = XN / 4;
    if (idx < X4) {
        srcp = x; dh = g_xh; dl = g_xl; off = idx;
    } else {
        int j = idx - X4;
        if (j < 4096)        { srcp = W0;  dh = g_w0h;  dl = g_w0l;  off = j; }
        else if (j < 8192)   { srcp = Wq1; dh = g_wq1h; dl = g_wq1l; off = j - 4096; }
        else if (j < 12288)  { srcp = Wp1; dh = g_wp1h; dl = g_wp1l; off = j - 8192; }
        else if (j < 14336)  { srcp = Wq2; dh = g_wq2h; dl = g_wq2l; off = j - 12288; }
        else if (j < 16384)  { srcp = Wp2; dh = g_wp2h; dl = g_wp2l; off = j - 14336; }
        else return;
    }
    float4 v = srcp[off];
    uint32_t h01, l01, h23, l23;
    split2(v.x, v.y, h01, l01);
    split2(v.z, v.w, h23, l23);
    *(uint2*)(dh + off * 4) = make_uint2(h01, h23);
    *(uint2*)(dl + off * 4) = make_uint2(l01, l23);
}

// ---------------- CSR build ----------------
__global__ void k_hist(const int* __restrict__ dst) {
    int t = blockIdx.x * blockDim.x + threadIdx.x;
    if (t < N_EDGES / 4) {
        int4 d = ((const int4*)dst)[t];
        atomicAdd(&g_cnt[d.x], 1);
        atomicAdd(&g_cnt[d.y], 1);
        atomicAdd(&g_cnt[d.z], 1);
        atomicAdd(&g_cnt[d.w], 1);
    }
}

__global__ void k_scan_part() {
    __shared__ int sd[256];
    int i = blockIdx.x * 256 + threadIdx.x;
    int v = (i < N_NODES) ? g_cnt[i] : 0;
    sd[threadIdx.x] = v;
    __syncthreads();
#pragma unroll
    for (int off = 128; off; off >>= 1) {
        if (threadIdx.x < off) sd[threadIdx.x] += sd[threadIdx.x + off];
        __syncthreads();
    }
    if (threadIdx.x == 0) g_part[blockIdx.x] = sd[0];
}

__global__ void k_scan_mid() {
    __shared__ int sd[256];
    int t = threadIdx.x;
    int v = (t < SCAN_BLOCKS) ? g_part[t] : 0;
    sd[t] = v;
    __syncthreads();
#pragma unroll
    for (int off = 1; off < 256; off <<= 1) {
        int u = (t >= off) ? sd[t - off] : 0;
        __syncthreads();
        sd[t] += u;
        __syncthreads();
    }
    if (t < SCAN_BLOCKS) g_partoff[t] = sd[t] - v;  // exclusive
}

__global__ void k_scan_final() {
    __shared__ int sd[256];
    int i = blockIdx.x * 256 + threadIdx.x;
    int t = threadIdx.x;
    int v = (i < N_NODES) ? g_cnt[i] : 0;
    sd[t] = v;
    __syncthreads();
#pragma unroll
    for (int off = 1; off < 256; off <<= 1) {
        int u = (t >= off) ? sd[t - off] : 0;
        __syncthreads();
        sd[t] += u;
        __syncthreads();
    }
    if (i < N_NODES) {
        int excl = g_partoff[blockIdx.x] + sd[t] - v;
        g_rowptr[i] = excl;
        g_fill[i] = excl;
    }
    if (i == N_NODES - 1) g_rowptr[N_NODES] = N_EDGES;
}

__global__ void k_scatter(const int* __restrict__ src, const int* __restrict__ dst) {
    int t = blockIdx.x * blockDim.x + threadIdx.x;
    if (t < N_EDGES / 4) {
        int4 d = ((const int4*)dst)[t];
        int4 s = ((const int4*)src)[t];
        g_csrc[atomicAdd(&g_fill[d.x], 1)] = s.x;
        g_csrc[atomicAdd(&g_fill[d.y], 1)] = s.y;
        g_csrc[atomicAdd(&g_fill[d.z], 1)] = s.z;
        g_csrc[atomicAdd(&g_fill[d.w], 1)] = s.w;
    }
}

// ---------------- static-smem mma.sync GEMM (R6/R10 proven; optional fp16 p-out) ----
template <int NO, bool ACT, bool SPLITOUT, bool PHALF>
__global__ __launch_bounds__(256, 2) void k_gemm(
    const __nv_bfloat16* __restrict__ Ah, const __nv_bfloat16* __restrict__ Al,
    const __nv_bfloat16* __restrict__ Wh0, const __nv_bfloat16* __restrict__ Wl0,
    const float* __restrict__ bias0, float* __restrict__ Cf0,
    __nv_bfloat16* __restrict__ Ch0, __nv_bfloat16* __restrict__ Cl0,
    const __nv_bfloat16* __restrict__ Wh1, const __nv_bfloat16* __restrict__ Wl1,
    const float* __restrict__ bias1, float* __restrict__ Cf1,
    __half* __restrict__ Ph, int M) {
    constexpr int AP = 40;
    constexpr int WPAD = NO + 8;
    constexpr int NB = NO / 16;

    const __nv_bfloat16* Wh = blockIdx.y ? Wh1 : Wh0;
    const __nv_bfloat16* Wl = blockIdx.y ? Wl1 : Wl0;
    const float* bias = blockIdx.y ? bias1 : bias0;
    float* Cf = blockIdx.y ? Cf1 : Cf0;

    __shared__ alignas(16) __nv_bfloat16 sAh[128 * AP];
    __shared__ alignas(16) __nv_bfloat16 sAl[128 * AP];
    __shared__ alignas(16) __nv_bfloat16 sWh[32 * WPAD];
    __shared__ alignas(16) __nv_bfloat16 sWl[32 * WPAD];

    const int tid = threadIdx.x;
    const int wid = tid >> 5, lane = tid & 31;
    const int wm = wid & 3, wn = wid >> 2;
    const int row0 = blockIdx.x * 128;

    float acc[2][NB][4];
#pragma unroll
    for (int mb = 0; mb < 2; mb++)
#pragma unroll
        for (int nb = 0; nb < NB; nb++)
#pragma unroll
            for (int j = 0; j < 4; j++) acc[mb][nb][j] = 0.f;

    const uint32_t aBaseH = smem_u32(sAh), aBaseL = smem_u32(sAl);
    const uint32_t wBaseH = smem_u32(sWh), wBaseL = smem_u32(sWl);

    const int a_row = wm * 32 + (lane & 15);
    const int a_col = (lane >> 4) * 8;
    const int b_blk = lane >> 3;
    const int b_rowoff = (b_blk & 1) * 8 + (lane & 7);
    const int b_coladd = wn * (NO / 2) + (b_blk >> 1) * 8;

    const uint4 z4 = make_uint4(0, 0, 0, 0);

    for (int c = 0; c < 4; c++) {
        const int k0 = c * 32;
        for (int i = tid; i < 512; i += 256) {
            int r = i >> 2, qq = i & 3;
            int grow = row0 + r;
            uint4 vh = z4, vl = z4;
            if (grow < M) {
                vh = *(const uint4*)(Ah + (size_t)grow * 128 + k0 + qq * 8);
                vl = *(const uint4*)(Al + (size_t)grow * 128 + k0 + qq * 8);
            }
            *(uint4*)(sAh + r * AP + qq * 8) = vh;
            *(uint4*)(sAl + r * AP + qq * 8) = vl;
        }
        for (int i = tid; i < 32 * NO / 8; i += 256) {
            int r = i / (NO / 8), off = (i % (NO / 8)) * 8;
            *(uint4*)(sWh + r * WPAD + off) = *(const uint4*)(Wh + (size_t)(k0 + r) * NO + off);
            *(uint4*)(sWl + r * WPAD + off) = *(const uint4*)(Wl + (size_t)(k0 + r) * NO + off);
        }
        __syncthreads();

#pragma unroll
        for (int kc = 0; kc < 32; kc += 16) {
            uint32_t ah[2][4], al[2][4];
#pragma unroll
            for (int mb = 0; mb < 2; mb++) {
                uint32_t off = (uint32_t)((a_row + mb * 16) * AP + kc + a_col) * 2;
                ldx4(ah[mb], aBaseH + off);
                ldx4(al[mb], aBaseL + off);
            }
#pragma unroll
            for (int nb = 0; nb < NB; nb += 2) {
                uint32_t bh[4], bl[4];
                uint32_t off = (uint32_t)((kc + b_rowoff) * WPAD + nb * 8 + b_coladd) * 2;
                ldx4t(bh, wBaseH + off);
                ldx4t(bl, wBaseL + off);
#pragma unroll
                for (int mb = 0; mb < 2; mb++) {
                    mma16816(acc[mb][nb], ah[mb], bh[0], bh[1]);
                    mma16816(acc[mb][nb + 1], ah[mb], bh[2], bh[3]);
                    mma16816(acc[mb][nb], ah[mb], bl[0], bl[1]);
                    mma16816(acc[mb][nb + 1], ah[mb], bl[2], bl[3]);
                    mma16816(acc[mb][nb], al[mb], bh[0], bh[1]);
                    mma16816(acc[mb][nb + 1], al[mb], bh[2], bh[3]);
                }
            }
        }
        __syncthreads();
    }

#pragma unroll
    for (int mb = 0; mb < 2; mb++) {
#pragma unroll
        for (int nb = 0; nb < NB; nb++) {
            int col = wn * (NO / 2) + nb * 8 + (lane & 3) * 2;
            float b0 = bias[col], b1 = bias[col + 1];
#pragma unroll
            for (int half = 0; half < 2; half++) {
                int r = row0 + wm * 32 + mb * 16 + (lane >> 2) + half * 8;
                if (r < M) {
                    float o0 = acc[mb][nb][half * 2 + 0] + b0;
                    float o1 = acc[mb][nb][half * 2 + 1] + b1;
                    if (ACT) { o0 = gelu_erf(o0); o1 = gelu_erf(o1); }
                    if (SPLITOUT) {
                        uint32_t hi, lo;
                        split2(o0, o1, hi, lo);
                        *(uint32_t*)(Ch0 + (size_t)r * NO + col) = hi;
                        *(uint32_t*)(Cl0 + (size_t)r * NO + col) = lo;
                    } else if (PHALF && blockIdx.y) {
                        *(__half2*)(Ph + (size_t)r * NO + col) = __floats2half2_rn(o0, o1);
                    } else {
                        *(float2*)(Cf + (size_t)r * NO + col) = make_float2(o0, o1);
                    }
                }
            }
        }
    }
}

// ---------------- GAT D=128: fp16 p gathers (one uint4/lane/edge) ----------------
__global__ __launch_bounds__(256) void k_gat128(const float* __restrict__ q,
                                                const __half* __restrict__ ph,
                                                const float* __restrict__ avec,
                                                const float* __restrict__ badd,
                                                __nv_bfloat16* __restrict__ outh,
                                                __nv_bfloat16* __restrict__ outl) {
    int w = (blockIdx.x * blockDim.x + threadIdx.x) >> 5;
    int lane = threadIdx.x & 31;
    if (w >= N_NODES) return;
    int half = lane >> 4, hl = lane & 15;

    const float4* q4 = (const float4*)q;
    const uint4* p16 = (const uint4*)ph;
    const float4* a4 = (const float4*)avec;
    float4 qv0 = q4[(size_t)w * 32 + hl * 2];
    float4 qv1 = q4[(size_t)w * 32 + hl * 2 + 1];
    float4 av0 = a4[hl * 2], av1 = a4[hl * 2 + 1];

    int beg = g_rowptr[w];
    int count = g_rowptr[w + 1] - beg;
    int n0 = (count + 1) >> 1;
    int base = beg + half * n0;
    int cnt_h = half ? (count - n0) : n0;

    float denom = 0.f;
    float s0 = 0.f, s1 = 0.f, s2 = 0.f, s3 = 0.f;
    float s4 = 0.f, s5 = 0.f, s6 = 0.f, s7 = 0.f;

    for (int it = 0; it < n0; it += 4) {
        bool act0 = it < cnt_h, act1 = it + 1 < cnt_h;
        bool act2 = it + 2 < cnt_h, act3 = it + 3 < cnt_h;
        int i0 = act0 ? g_csrc[base + it] : 0;
        int i1 = act1 ? g_csrc[base + it + 1] : 0;
        int i2 = act2 ? g_csrc[base + it + 2] : 0;
        int i3 = act3 ? g_csrc[base + it + 3] : 0;
        float4 pA0, pA1, pB0, pB1, pC0, pC1, pD0, pD1;
        ld_p16(p16, i0, hl, pA0, pA1);
        ld_p16(p16, i1, hl, pB0, pB1);
        ld_p16(p16, i2, hl, pC0, pC1);
        ld_p16(p16, i3, hl, pD0, pD1);

        float pa = LRELU(qv0.x + pA0.x) * av0.x + LRELU(qv0.y + pA0.y) * av0.y +
                   LRELU(qv0.z + pA0.z) * av0.z + LRELU(qv0.w + pA0.w) * av0.w +
                   LRELU(qv1.x + pA1.x) * av1.x + LRELU(qv1.y + pA1.y) * av1.y +
                   LRELU(qv1.z + pA1.z) * av1.z + LRELU(qv1.w + pA1.w) * av1.w;
        float pb = LRELU(qv0.x + pB0.x) * av0.x + LRELU(qv0.y + pB0.y) * av0.y +
                   LRELU(qv0.z + pB0.z) * av0.z + LRELU(qv0.w + pB0.w) * av0.w +
                   LRELU(qv1.x + pB1.x) * av1.x + LRELU(qv1.y + pB1.y) * av1.y +
                   LRELU(qv1.z + pB1.z) * av1.z + LRELU(qv1.w + pB1.w) * av1.w;
        float pc = LRELU(qv0.x + pC0.x) * av0.x + LRELU(qv0.y + pC0.y) * av0.y +
                   LRELU(qv0.z + pC0.z) * av0.z + LRELU(qv0.w + pC0.w) * av0.w +
                   LRELU(qv1.x + pC1.x) * av1.x + LRELU(qv1.y + pC1.y) * av1.y +
                   LRELU(qv1.z + pC1.z) * av1.z + LRELU(qv1.w + pC1.w) * av1.w;
        float pd = LRELU(qv0.x + pD0.x) * av0.x + LRELU(qv0.y + pD0.y) * av0.y +
                   LRELU(qv0.z + pD0.z) * av0.z + LRELU(qv0.w + pD0.w) * av0.w +
                   LRELU(qv1.x + pD1.x) * av1.x + LRELU(qv1.y + pD1.y) * av1.y +
                   LRELU(qv1.z + pD1.z) * av1.z + LRELU(qv1.w + pD1.w) * av1.w;

#pragma unroll
        for (int o = 8; o; o >>= 1) {
            pa += __shfl_xor_sync(0xffffffffu, pa, o);
            pb += __shfl_xor_sync(0xffffffffu, pb, o);
            pc += __shfl_xor_sync(0xffffffffu, pc, o);
            pd += __shfl_xor_sync(0xffffffffu, pd, o);
        }
        float eA = act0 ? __expf(pa) : 0.f;
        float eB = act1 ? __expf(pb) : 0.f;
        float eC = act2 ? __expf(pc) : 0.f;
        float eD = act3 ? __expf(pd) : 0.f;
        denom += (eA + eB) + (eC + eD);
        s0 = fmaf(eA, pA0.x, fmaf(eB, pB0.x, fmaf(eC, pC0.x, fmaf(eD, pD0.x, s0))));
        s1 = fmaf(eA, pA0.y, fmaf(eB, pB0.y, fmaf(eC, pC0.y, fmaf(eD, pD0.y, s1))));
        s2 = fmaf(eA, pA0.z, fmaf(eB, pB0.z, fmaf(eC, pC0.z, fmaf(eD, pD0.z, s2))));
        s3 = fmaf(eA, pA0.w, fmaf(eB, pB0.w, fmaf(eC, pC0.w, fmaf(eD, pD0.w, s3))));
        s4 = fmaf(eA, pA1.x, fmaf(eB, pB1.x, fmaf(eC, pC1.x, fmaf(eD, pD1.x, s4))));
        s5 = fmaf(eA, pA1.y, fmaf(eB, pB1.y, fmaf(eC, pC1.y, fmaf(eD, pD1.y, s5))));
        s6 = fmaf(eA, pA1.z, fmaf(eB, pB1.z, fmaf(eC, pC1.z, fmaf(eD, pD1.z, s6))));
        s7 = fmaf(eA, pA1.w, fmaf(eB, pB1.w, fmaf(eC, pC1.w, fmaf(eD, pD1.w, s7))));
    }
    denom += __shfl_xor_sync(0xffffffffu, denom, 16);
    s0 += __shfl_xor_sync(0xffffffffu, s0, 16);
    s1 += __shfl_xor_sync(0xffffffffu, s1, 16);
    s2 += __shfl_xor_sync(0xffffffffu, s2, 16);
    s3 += __shfl_xor_sync(0xffffffffu, s3, 16);
    s4 += __shfl_xor_sync(0xffffffffu, s4, 16);
    s5 += __shfl_xor_sync(0xffffffffu, s5, 16);
    s6 += __shfl_xor_sync(0xffffffffu, s6, 16);
    s7 += __shfl_xor_sync(0xffffffffu, s7, 16);

    if (half == 0) {
        float inv = (count > 0) ? 1.f / denom : 0.f;
        int col = hl * 8;
        float v0 = gelu_erf(fmaf(s0, inv, badd[col + 0]));
        float v1 = gelu_erf(fmaf(s1, inv, badd[col + 1]));
        float v2 = gelu_erf(fmaf(s2, inv, badd[col + 2]));
        float v3 = gelu_erf(fmaf(s3, inv, badd[col + 3]));
        float v4 = gelu_erf(fmaf(s4, inv, badd[col + 4]));
        float v5 = gelu_erf(fmaf(s5, inv, badd[col + 5]));
        float v6 = gelu_erf(fmaf(s6, inv, badd[col + 6]));
        float v7 = gelu_erf(fmaf(s7, inv, badd[col + 7]));
        uint32_t h01, l01, h23, l23, h45, l45, h67, l67;
        split2(v0, v1, h01, l01);
        split2(v2, v3, h23, l23);
        split2(v4, v5, h45, l45);
        split2(v6, v7, h67, l67);
        *(uint4*)(outh + (size_t)w * 128 + col) = make_uint4(h01, h23, h45, h67);
        *(uint4*)(outl + (size_t)w * 128 + col) = make_uint4(l01, l23, l45, l67);
    }
}

// ---------------- GAT D=64 (R10 proven, fp32 p2) ----------------
__global__ __launch_bounds__(256) void k_gat64(const float* __restrict__ q,
                                               const float* __restrict__ p,
                                               const float* __restrict__ avec,
                                               const float* __restrict__ bout,
                                               float* __restrict__ out) {
    int w = (blockIdx.x * blockDim.x + threadIdx.x) >> 5;
    int lane = threadIdx.x & 31;
    if (w >= N_NODES) return;
    int half = lane >> 4, hl = lane & 15;

    const float4* q4 = (const float4*)q;
    const float4* p4 = (const float4*)p;
    float4 qv = q4[(size_t)w * 16 + hl];
    float4 av = ((const float4*)avec)[hl];

    int beg = g_rowptr[w];
    int count = g_rowptr[w + 1] - beg;
    int n0 = (count + 1) >> 1;
    int base = beg + half * n0;
    int cnt_h = half ? (count - n0) : n0;

    float denom = 0.f;
    float s0 = 0.f, s1 = 0.f, s2 = 0.f, s3 = 0.f;

    for (int it = 0; it < n0; it += 4) {
        bool act0 = it < cnt_h, act1 = it + 1 < cnt_h;
        bool act2 = it + 2 < cnt_h, act3 = it + 3 < cnt_h;
        int i0 = act0 ? g_csrc[base + it] : 0;
        int i1 = act1 ? g_csrc[base + it + 1] : 0;
        int i2 = act2 ? g_csrc[base + it + 2] : 0;
        int i3 = act3 ? g_csrc[base + it + 3] : 0;
        float4 pA = p4[(size_t)i0 * 16 + hl];
        float4 pB = p4[(size_t)i1 * 16 + hl];
        float4 pC = p4[(size_t)i2 * 16 + hl];
        float4 pD = p4[(size_t)i3 * 16 + hl];

        float pa = LRELU(qv.x + pA.x) * av.x + LRELU(qv.y + pA.y) * av.y +
                   LRELU(qv.z + pA.z) * av.z + LRELU(qv.w + pA.w) * av.w;
        float pb = LRELU(qv.x + pB.x) * av.x + LRELU(qv.y + pB.y) * av.y +
                   LRELU(qv.z + pB.z) * av.z + LRELU(qv.w + pB.w) * av.w;
        float pc = LRELU(qv.x + pC.x) * av.x + LRELU(qv.y + pC.y) * av.y +
                   LRELU(qv.z + pC.z) * av.z + LRELU(qv.w + pC.w) * av.w;
        float pd = LRELU(qv.x + pD.x) * av.x + LRELU(qv.y + pD.y) * av.y +
                   LRELU(qv.z + pD.z) * av.z + LRELU(qv.w + pD.w) * av.w;

#pragma unroll
        for (int o = 8; o; o >>= 1) {
            pa += __shfl_xor_sync(0xffffffffu, pa, o);
            pb += __shfl_xor_sync(0xffffffffu, pb, o);
            pc += __shfl_xor_sync(0xffffffffu, pc, o);
            pd += __shfl_xor_sync(0xffffffffu, pd, o);
        }
        float eA = act0 ? __expf(pa) : 0.f;
        float eB = act1 ? __expf(pb) : 0.f;
        float eC = act2 ? __expf(pc) : 0.f;
        float eD = act3 ? __expf(pd) : 0.f;
        denom += (eA + eB) + (eC + eD);
        s0 = fmaf(eA, pA.x, fmaf(eB, pB.x, fmaf(eC, pC.x, fmaf(eD, pD.x, s0))));
        s1 = fmaf(eA, pA.y, fmaf(eB, pB.y, fmaf(eC, pC.y, fmaf(eD, pD.y, s1))));
        s2 = fmaf(eA, pA.z, fmaf(eB, pB.z, fmaf(eC, pC.z, fmaf(eD, pD.z, s2))));
        s3 = fmaf(eA, pA.w, fmaf(eB, pB.w, fmaf(eC, pC.w, fmaf(eD, pD.w, s3))));
    }
    denom += __shfl_xor_sync(0xffffffffu, denom, 16);
    s0 += __shfl_xor_sync(0xffffffffu, s0, 16);
    s1 += __shfl_xor_sync(0xffffffffu, s1, 16);
    s2 += __shfl_xor_sync(0xffffffffu, s2, 16);
    s3 += __shfl_xor_sync(0xffffffffu, s3, 16);

    if (half == 0) {
        float inv = (count > 0) ? 1.f / denom : 0.f;
        int col = hl * 4;
        float4 o;
        o.x = fmaf(s0, inv, bout[col + 0]);
        o.y = fmaf(s1, inv, bout[col + 1]);
        o.z = fmaf(s2, inv, bout[col + 2]);
        o.w = fmaf(s3, inv, bout[col + 3]);
        ((float4*)out)[(size_t)w * 16 + hl] = o;
    }
}

// ---------------- launch (R10 schedule) ----------------
extern "C" void kernel_launch(void* const* d_in, const int* in_sizes, int n_in,
                              void* d_out, int out_size) {
    const float* x    = (const float*)d_in[0];
    const float* W0   = (const float*)d_in[1];
    const float* b0   = (const float*)d_in[2];
    const float* Wq1  = (const float*)d_in[3];
    const float* bq1  = (const float*)d_in[4];
    const float* Wp1  = (const float*)d_in[5];
    const float* bp1  = (const float*)d_in[6];
    const float* a1   = (const float*)d_in[7];
    const float* bg2  = (const float*)d_in[8];
    const float* Wq2  = (const float*)d_in[9];
    const float* bq2  = (const float*)d_in[10];
    const float* Wp2  = (const float*)d_in[11];
    const float* bp2  = (const float*)d_in[12];
    const float* a2   = (const float*)d_in[13];
    const float* b_out= (const float*)d_in[14];
    const int*   src  = (const int*)d_in[15];
    const int*   dst  = (const int*)d_in[16];

    float *q1, *q2, *p2;
    __half* p1h;
    cudaGetSymbolAddress((void**)&q1, g_q1);
    cudaGetSymbolAddress((void**)&p1h, g_p1h);
    cudaGetSymbolAddress((void**)&q2, g_q2);
    cudaGetSymbolAddress((void**)&p2, g_p2);

    __nv_bfloat16 *xh, *xl, *m1h, *m1l, *m2h, *m2l;
    cudaGetSymbolAddress((void**)&xh, g_xh);
    cudaGetSymbolAddress((void**)&xl, g_xl);
    cudaGetSymbolAddress((void**)&m1h, g_m1h);
    cudaGetSymbolAddress((void**)&m1l, g_m1l);
    cudaGetSymbolAddress((void**)&m2h, g_m2h);
    cudaGetSymbolAddress((void**)&m2l, g_m2l);

    __nv_bfloat16 *w0h, *w0l, *wq1h, *wq1l, *wp1h, *wp1l, *wq2h, *wq2l, *wp2h, *wp2l;
    cudaGetSymbolAddress((void**)&w0h, g_w0h);
    cudaGetSymbolAddress((void**)&w0l, g_w0l);
    cudaGetSymbolAddress((void**)&wq1h, g_wq1h);
    cudaGetSymbolAddress((void**)&wq1l, g_wq1l);
    cudaGetSymbolAddress((void**)&wp1h, g_wp1h);
    cudaGetSymbolAddress((void**)&wp1l, g_wp1l);
    cudaGetSymbolAddress((void**)&wq2h, g_wq2h);
    cudaGetSymbolAddress((void**)&wq2l, g_wq2l);
    cudaGetSymbolAddress((void**)&wp2h, g_wp2h);
    cudaGetSymbolAddress((void**)&wp2l, g_wp2l);

    int* cntp;
    cudaGetSymbolAddress((void**)&cntp, g_cnt);

    const int gemm_gx = (N_NODES + 127) / 128;  // 391
    const dim3 qp_grid(gemm_gx, 2);
    const int gat_grid = (N_NODES + 7) / 8;     // 6250
    const int e4_grid = (N_EDGES / 4 + 255) / 256;

    // side stream for CSR build (overlaps with prep + layer-1 GEMMs)
    cudaStream_t s2;
    cudaStreamCreateWithFlags(&s2, cudaStreamNonBlocking);
    cudaEvent_t eFork, eJoin;
    cudaEventCreateWithFlags(&eFork, cudaEventDisableTiming);
    cudaEventCreateWithFlags(&eJoin, cudaEventDisableTiming);

    cudaEventRecord(eFork, 0);
    cudaStreamWaitEvent(s2, eFork, 0);

    cudaMemsetAsync(cntp, 0, N_NODES * sizeof(int), s2);
    k_hist<<<e4_grid, 256, 0, s2>>>(dst);
    k_scan_part<<<SCAN_BLOCKS, 256, 0, s2>>>();
    k_scan_mid<<<1, 256, 0, s2>>>();
    k_scan_final<<<SCAN_BLOCKS, 256, 0, s2>>>();
    k_scatter<<<e4_grid, 256, 0, s2>>>(src, dst);
    cudaEventRecord(eJoin, s2);

    // main chain
    k_prep_all<<<(XN / 4 + 16384 + 255) / 256, 256>>>(
        (const float4*)x, (const float4*)W0, (const float4*)Wq1,
        (const float4*)Wp1, (const float4*)Wq2, (const float4*)Wp2);
    k_gemm<128, true, true, false><<<gemm_gx, 256>>>(
        xh, xl, w0h, w0l, b0, nullptr, m1h, m1l,
        w0h, w0l, b0, nullptr, nullptr, N_NODES);
    k_gemm<128, false, false, true><<<qp_grid, 256>>>(
        m1h, m1l, wq1h, wq1l, bq1, q1, nullptr, nullptr,
        wp1h, wp1l, bp1, nullptr, p1h, N_NODES);

    cudaStreamWaitEvent(0, eJoin, 0);
    k_gat128<<<gat_grid, 256>>>(q1, p1h, a1, bg2, m2h, m2l);

    k_gemm<64, false, false, false><<<qp_grid, 256>>>(
        m2h, m2l, wq2h, wq2l, bq2, q2, nullptr, nullptr,
        wp2h, wp2l, bp2, p2, nullptr, N_NODES);
    k_gat64<<<gat_grid, 256>>>(q2, p2, a2, b_out, (float*)d_out);

    cudaEventDestroy(eFork);
    cudaEventDestroy(eJoin);
    cudaStreamDestroy(s2);
}

// round 15
// speedup vs baseline: 1.5483x; 1.5483x over previous
#include <cuda_runtime.h>
#include <cuda_bf16.h>
#include <math.h>
#include <stdint.h>

#define N_NODES 50000
#define N_EDGES 800000
#define DH 128
#define DOUT 64
#define XN (N_NODES * DH)
#define SCAN_BLOCKS 196   // 196*256 = 50176 >= N_NODES

// ---------------- scratch (device globals) ----------------
__device__ __nv_bfloat16 g_xh[XN], g_xl[XN];
__device__ __nv_bfloat16 g_m1b[XN];              // m1 as plain bf16 (2-split path)
__device__ __nv_bfloat16 g_m2h[XN], g_m2l[XN];   // m2 split (3-split gemm2)
__device__ float g_q1[N_NODES * DH];
__device__ float g_p1[N_NODES * DH];
__device__ float g_q2[N_NODES * DOUT];
__device__ float g_p2[N_NODES * DOUT];
__device__ int   g_cnt[N_NODES];
__device__ int   g_fill[N_NODES];
__device__ int   g_rowptr[N_NODES + 1];
__device__ int   g_csrc[N_EDGES];
__device__ int   g_part[SCAN_BLOCKS];
__device__ int   g_partoff[SCAN_BLOCKS];

__device__ __nv_bfloat16 g_w0h[128 * 128], g_w0l[128 * 128];
__device__ __nv_bfloat16 g_wq1h[128 * 128], g_wq1l[128 * 128];
__device__ __nv_bfloat16 g_wp1h[128 * 128], g_wp1l[128 * 128];
__device__ __nv_bfloat16 g_wq2h[128 * 64], g_wq2l[128 * 64];
__device__ __nv_bfloat16 g_wp2h[128 * 64], g_wp2l[128 * 64];

// ---------------- helpers ----------------
__device__ __forceinline__ float gelu_erf(float x) {
    return 0.5f * x * (1.0f + erff(x * 0.70710678118654752440f));
}

__device__ __forceinline__ uint32_t smem_u32(const void* p) {
    uint32_t a;
    asm("{ .reg .u64 t; cvta.to.shared.u64 t, %1; cvt.u32.u64 %0, t; }" : "=r"(a) : "l"(p));
    return a;
}

__device__ __forceinline__ void ldx4(uint32_t* r, uint32_t addr) {
    asm volatile("ldmatrix.sync.aligned.m8n8.x4.shared.b16 {%0,%1,%2,%3}, [%4];"
                 : "=r"(r[0]), "=r"(r[1]), "=r"(r[2]), "=r"(r[3]) : "r"(addr));
}

__device__ __forceinline__ void ldx4t(uint32_t* r, uint32_t addr) {
    asm volatile("ldmatrix.sync.aligned.m8n8.x4.trans.shared.b16 {%0,%1,%2,%3}, [%4];"
                 : "=r"(r[0]), "=r"(r[1]), "=r"(r[2]), "=r"(r[3]) : "r"(addr));
}

__device__ __forceinline__ void mma16816(float* c, const uint32_t* a, uint32_t b0, uint32_t b1) {
    asm volatile(
        "mma.sync.aligned.m16n8k16.row.col.f32.bf16.bf16.f32 "
        "{%0,%1,%2,%3}, {%4,%5,%6,%7}, {%8,%9}, {%0,%1,%2,%3};"
        : "+f"(c[0]), "+f"(c[1]), "+f"(c[2]), "+f"(c[3])
        : "r"(a[0]), "r"(a[1]), "r"(a[2]), "r"(a[3]), "r"(b0), "r"(b1));
}

__device__ __forceinline__ void split2(float a, float b, uint32_t& hi, uint32_t& lo) {
    __nv_bfloat16 ha = __float2bfloat16(a), hb = __float2bfloat16(b);
    __nv_bfloat16 la = __float2bfloat16(a - __bfloat162float(ha));
    __nv_bfloat16 lb = __float2bfloat16(b - __bfloat162float(hb));
    hi = (uint32_t)__bfloat16_as_ushort(ha) | ((uint32_t)__bfloat16_as_ushort(hb) << 16);
    lo = (uint32_t)__bfloat16_as_ushort(la) | ((uint32_t)__bfloat16_as_ushort(lb) << 16);
}

__device__ __forceinline__ uint32_t pack_bf16(float a, float b) {
    return (uint32_t)__bfloat16_as_ushort(__float2bfloat16(a)) |
           ((uint32_t)__bfloat16_as_ushort(__float2bfloat16(b)) << 16);
}

#define LRELU(d) ((d) > 0.f ? (d) : 0.2f * (d))

// ---------------- merged prep (float4 vectorized) ----------------
__global__ void k_prep_all(const float4* __restrict__ x,
                           const float4* __restrict__ W0, const float4* __restrict__ Wq1,
                           const float4* __restrict__ Wp1, const float4* __restrict__ Wq2,
                           const float4* __restrict__ Wp2) {
    int idx = blockIdx.x * blockDim.x + threadIdx.x;
    const float4* srcp;
    __nv_bfloat16 *dh, *dl;
    int off;
    const int X4 = XN / 4;
    if (idx < X4) {
        srcp = x; dh = g_xh; dl = g_xl; off = idx;
    } else {
        int j = idx - X4;
        if (j < 4096)        { srcp = W0;  dh = g_w0h;  dl = g_w0l;  off = j; }
        else if (j < 8192)   { srcp = Wq1; dh = g_wq1h; dl = g_wq1l; off = j - 4096; }
        else if (j < 12288)  { srcp = Wp1; dh = g_wp1h; dl = g_wp1l; off = j - 8192; }
        else if (j < 14336)  { srcp = Wq2; dh = g_wq2h; dl = g_wq2l; off = j - 12288; }
        else if (j < 16384)  { srcp = Wp2; dh = g_wp2h; dl = g_wp2l; off = j - 14336; }
        else return;
    }
    float4 v = srcp[off];
    uint32_t h01, l01, h23, l23;
    split2(v.x, v.y, h01, l01);
    split2(v.z, v.w, h23, l23);
    *(uint2*)(dh + off * 4) = make_uint2(h01, h23);
    *(uint2*)(dl + off * 4) = make_uint2(l01, l23);
}

// ---------------- CSR build ----------------
__global__ void k_hist(const int* __restrict__ dst) {
    int t = blockIdx.x * blockDim.x + threadIdx.x;
    if (t < N_EDGES / 4) {
        int4 d = ((const int4*)dst)[t];
        atomicAdd(&g_cnt[d.x], 1);
        atomicAdd(&g_cnt[d.y], 1);
        atomicAdd(&g_cnt[d.z], 1);
        atomicAdd(&g_cnt[d.w], 1);
    }
}

__global__ void k_scan_part() {
    __shared__ int sd[256];
    int i = blockIdx.x * 256 + threadIdx.x;
    int v = (i < N_NODES) ? g_cnt[i] : 0;
    sd[threadIdx.x] = v;
    __syncthreads();
#pragma unroll
    for (int off = 128; off; off >>= 1) {
        if (threadIdx.x < off) sd[threadIdx.x] += sd[threadIdx.x + off];
        __syncthreads();
    }
    if (threadIdx.x == 0) g_part[blockIdx.x] = sd[0];
}

__global__ void k_scan_mid() {
    __shared__ int sd[256];
    int t = threadIdx.x;
    int v = (t < SCAN_BLOCKS) ? g_part[t] : 0;
    sd[t] = v;
    __syncthreads();
#pragma unroll
    for (int off = 1; off < 256; off <<= 1) {
        int u = (t >= off) ? sd[t - off] : 0;
        __syncthreads();
        sd[t] += u;
        __syncthreads();
    }
    if (t < SCAN_BLOCKS) g_partoff[t] = sd[t] - v;  // exclusive
}

__global__ void k_scan_final() {
    __shared__ int sd[256];
    int i = blockIdx.x * 256 + threadIdx.x;
    int t = threadIdx.x;
    int v = (i < N_NODES) ? g_cnt[i] : 0;
    sd[t] = v;
    __syncthreads();
#pragma unroll
    for (int off = 1; off < 256; off <<= 1) {
        int u = (t >= off) ? sd[t - off] : 0;
        __syncthreads();
        sd[t] += u;
        __syncthreads();
    }
    if (i < N_NODES) {
        int excl = g_partoff[blockIdx.x] + sd[t] - v;
        g_rowptr[i] = excl;
        g_fill[i] = excl;
    }
    if (i == N_NODES - 1) g_rowptr[N_NODES] = N_EDGES;
}

__global__ void k_scatter(const int* __restrict__ src, const int* __restrict__ dst) {
    int t = blockIdx.x * blockDim.x + threadIdx.x;
    if (t < N_EDGES / 4) {
        int4 d = ((const int4*)dst)[t];
        int4 s = ((const int4*)src)[t];
        g_csrc[atomicAdd(&g_fill[d.x], 1)] = s.x;
        g_csrc[atomicAdd(&g_fill[d.y], 1)] = s.y;
        g_csrc[atomicAdd(&g_fill[d.z], 1)] = s.z;
        g_csrc[atomicAdd(&g_fill[d.w], 1)] = s.w;
    }
}

// ---------------- 2-split GEMM: C = act(A[M,128] @ (Wh+Wl) + bias) ----------------
// A is plain bf16 (exact); W in hi/lo split. 32 MMAs per k-chunk.
template <int NO, bool ACT, bool OUTB16>
__global__ __launch_bounds__(256, 2) void k_gemm2s(
    const __nv_bfloat16* __restrict__ A,
    const __nv_bfloat16* __restrict__ Wh0, const __nv_bfloat16* __restrict__ Wl0,
    const float* __restrict__ bias0, float* __restrict__ Cf0,
    __nv_bfloat16* __restrict__ Cb0,
    const __nv_bfloat16* __restrict__ Wh1, const __nv_bfloat16* __restrict__ Wl1,
    const float* __restrict__ bias1, float* __restrict__ Cf1, int M) {
    constexpr int AP = 40;
    constexpr int WPAD = NO + 8;
    constexpr int NB = NO / 16;

    const __nv_bfloat16* Wh = blockIdx.y ? Wh1 : Wh0;
    const __nv_bfloat16* Wl = blockIdx.y ? Wl1 : Wl0;
    const float* bias = blockIdx.y ? bias1 : bias0;
    float* Cf = blockIdx.y ? Cf1 : Cf0;

    __shared__ alignas(16) __nv_bfloat16 sA[128 * AP];
    __shared__ alignas(16) __nv_bfloat16 sWh[32 * WPAD];
    __shared__ alignas(16) __nv_bfloat16 sWl[32 * WPAD];

    const int tid = threadIdx.x;
    const int wid = tid >> 5, lane = tid & 31;
    const int wm = wid & 3, wn = wid >> 2;
    const int row0 = blockIdx.x * 128;

    float acc[2][NB][4];
#pragma unroll
    for (int mb = 0; mb < 2; mb++)
#pragma unroll
        for (int nb = 0; nb < NB; nb++)
#pragma unroll
            for (int j = 0; j < 4; j++) acc[mb][nb][j] = 0.f;

    const uint32_t aBase = smem_u32(sA);
    const uint32_t wBaseH = smem_u32(sWh), wBaseL = smem_u32(sWl);

    const int a_row = wm * 32 + (lane & 15);
    const int a_col = (lane >> 4) * 8;
    const int b_blk = lane >> 3;
    const int b_rowoff = (b_blk & 1) * 8 + (lane & 7);
    const int b_coladd = wn * (NO / 2) + (b_blk >> 1) * 8;

    const uint4 z4 = make_uint4(0, 0, 0, 0);

    for (int c = 0; c < 4; c++) {
        const int k0 = c * 32;
        for (int i = tid; i < 512; i += 256) {
            int r = i >> 2, qq = i & 3;
            int grow = row0 + r;
            uint4 va = z4;
            if (grow < M) va = *(const uint4*)(A + (size_t)grow * 128 + k0 + qq * 8);
            *(uint4*)(sA + r * AP + qq * 8) = va;
        }
        for (int i = tid; i < 32 * NO / 8; i += 256) {
            int r = i / (NO / 8), off = (i % (NO / 8)) * 8;
            *(uint4*)(sWh + r * WPAD + off) = *(const uint4*)(Wh + (size_t)(k0 + r) * NO + off);
            *(uint4*)(sWl + r * WPAD + off) = *(const uint4*)(Wl + (size_t)(k0 + r) * NO + off);
        }
        __syncthreads();

#pragma unroll
        for (int kc = 0; kc < 32; kc += 16) {
            uint32_t ah[2][4];
#pragma unroll
            for (int mb = 0; mb < 2; mb++) {
                uint32_t off = (uint32_t)((a_row + mb * 16) * AP + kc + a_col) * 2;
                ldx4(ah[mb], aBase + off);
            }
#pragma unroll
            for (int nb = 0; nb < NB; nb += 2) {
                uint32_t bh[4], bl[4];
                uint32_t off = (uint32_t)((kc + b_rowoff) * WPAD + nb * 8 + b_coladd) * 2;
                ldx4t(bh, wBaseH + off);
                ldx4t(bl, wBaseL + off);
#pragma unroll
                for (int mb = 0; mb < 2; mb++) {
                    mma16816(acc[mb][nb], ah[mb], bh[0], bh[1]);
                    mma16816(acc[mb][nb + 1], ah[mb], bh[2], bh[3]);
                    mma16816(acc[mb][nb], ah[mb], bl[0], bl[1]);
                    mma16816(acc[mb][nb + 1], ah[mb], bl[2], bl[3]);
                }
            }
        }
        __syncthreads();
    }

#pragma unroll
    for (int mb = 0; mb < 2; mb++) {
#pragma unroll
        for (int nb = 0; nb < NB; nb++) {
            int col = wn * (NO / 2) + nb * 8 + (lane & 3) * 2;
            float b0 = bias[col], b1 = bias[col + 1];
#pragma unroll
            for (int half = 0; half < 2; half++) {
                int r = row0 + wm * 32 + mb * 16 + (lane >> 2) + half * 8;
                if (r < M) {
                    float o0 = acc[mb][nb][half * 2 + 0] + b0;
                    float o1 = acc[mb][nb][half * 2 + 1] + b1;
                    if (ACT) { o0 = gelu_erf(o0); o1 = gelu_erf(o1); }
                    if (OUTB16) {
                        *(uint32_t*)(Cb0 + (size_t)r * NO + col) = pack_bf16(o0, o1);
                    } else {
                        *(float2*)(Cf + (size_t)r * NO + col) = make_float2(o0, o1);
                    }
                }
            }
        }
    }
}

// ---------------- 3-split GEMM (R10 proven; layer 2 only) ----------------
template <int NO>
__global__ __launch_bounds__(256, 2) void k_gemm3s(
    const __nv_bfloat16* __restrict__ Ah, const __nv_bfloat16* __restrict__ Al,
    const __nv_bfloat16* __restrict__ Wh0, const __nv_bfloat16* __restrict__ Wl0,
    const float* __restrict__ bias0, float* __restrict__ Cf0,
    const __nv_bfloat16* __restrict__ Wh1, const __nv_bfloat16* __restrict__ Wl1,
    const float* __restrict__ bias1, float* __restrict__ Cf1, int M) {
    constexpr int AP = 40;
    constexpr int WPAD = NO + 8;
    constexpr int NB = NO / 16;

    const __nv_bfloat16* Wh = blockIdx.y ? Wh1 : Wh0;
    const __nv_bfloat16* Wl = blockIdx.y ? Wl1 : Wl0;
    const float* bias = blockIdx.y ? bias1 : bias0;
    float* Cf = blockIdx.y ? Cf1 : Cf0;

    __shared__ alignas(16) __nv_bfloat16 sAh[128 * AP];
    __shared__ alignas(16) __nv_bfloat16 sAl[128 * AP];
    __shared__ alignas(16) __nv_bfloat16 sWh[32 * WPAD];
    __shared__ alignas(16) __nv_bfloat16 sWl[32 * WPAD];

    const int tid = threadIdx.x;
    const int wid = tid >> 5, lane = tid & 31;
    const int wm = wid & 3, wn = wid >> 2;
    const int row0 = blockIdx.x * 128;

    float acc[2][NB][4];
#pragma unroll
    for (int mb = 0; mb < 2; mb++)
#pragma unroll
        for (int nb = 0; nb < NB; nb++)
#pragma unroll
            for (int j = 0; j < 4; j++) acc[mb][nb][j] = 0.f;

    const uint32_t aBaseH = smem_u32(sAh), aBaseL = smem_u32(sAl);
    const uint32_t wBaseH = smem_u32(sWh), wBaseL = smem_u32(sWl);

    const int a_row = wm * 32 + (lane & 15);
    const int a_col = (lane >> 4) * 8;
    const int b_blk = lane >> 3;
    const int b_rowoff = (b_blk & 1) * 8 + (lane & 7);
    const int b_coladd = wn * (NO / 2) + (b_blk >> 1) * 8;

    const uint4 z4 = make_uint4(0, 0, 0, 0);

    for (int c = 0; c < 4; c++) {
        const int k0 = c * 32;
        for (int i = tid; i < 512; i += 256) {
            int r = i >> 2, qq = i & 3;
            int grow = row0 + r;
            uint4 vh = z4, vl = z4;
            if (grow < M) {
                vh = *(const uint4*)(Ah + (size_t)grow * 128 + k0 + qq * 8);
                vl = *(const uint4*)(Al + (size_t)grow * 128 + k0 + qq * 8);
            }
            *(uint4*)(sAh + r * AP + qq * 8) = vh;
            *(uint4*)(sAl + r * AP + qq * 8) = vl;
        }
        for (int i = tid; i < 32 * NO / 8; i += 256) {
            int r = i / (NO / 8), off = (i % (NO / 8)) * 8;
            *(uint4*)(sWh + r * WPAD + off) = *(const uint4*)(Wh + (size_t)(k0 + r) * NO + off);
            *(uint4*)(sWl + r * WPAD + off) = *(const uint4*)(Wl + (size_t)(k0 + r) * NO + off);
        }
        __syncthreads();

#pragma unroll
        for (int kc = 0; kc < 32; kc += 16) {
            uint32_t ah[2][4], al[2][4];
#pragma unroll
            for (int mb = 0; mb < 2; mb++) {
                uint32_t off = (uint32_t)((a_row + mb * 16) * AP + kc + a_col) * 2;
                ldx4(ah[mb], aBaseH + off);
                ldx4(al[mb], aBaseL + off);
            }
#pragma unroll
            for (int nb = 0; nb < NB; nb += 2) {
                uint32_t bh[4], bl[4];
                uint32_t off = (uint32_t)((kc + b_rowoff) * WPAD + nb * 8 + b_coladd) * 2;
                ldx4t(bh, wBaseH + off);
                ldx4t(bl, wBaseL + off);
#pragma unroll
                for (int mb = 0; mb < 2; mb++) {
                    mma16816(acc[mb][nb], ah[mb], bh[0], bh[1]);
                    mma16816(acc[mb][nb + 1], ah[mb], bh[2], bh[3]);
                    mma16816(acc[mb][nb], ah[mb], bl[0], bl[1]);
                    mma16816(acc[mb][nb + 1], ah[mb], bl[2], bl[3]);
                    mma16816(acc[mb][nb], al[mb], bh[0], bh[1]);
                    mma16816(acc[mb][nb + 1], al[mb], bh[2], bh[3]);
                }
            }
        }
        __syncthreads();
    }

#pragma unroll
    for (int mb = 0; mb < 2; mb++) {
#pragma unroll
        for (int nb = 0; nb < NB; nb++) {
            int col = wn * (NO / 2) + nb * 8 + (lane & 3) * 2;
            float b0 = bias[col], b1 = bias[col + 1];
#pragma unroll
            for (int half = 0; half < 2; half++) {
                int r = row0 + wm * 32 + mb * 16 + (lane >> 2) + half * 8;
                if (r < M) {
                    float o0 = acc[mb][nb][half * 2 + 0] + b0;
                    float o1 = acc[mb][nb][half * 2 + 1] + b1;
                    *(float2*)(Cf + (size_t)r * NO + col) = make_float2(o0, o1);
                }
            }
        }
    }
}

// ---------------- GAT D=128 (R10 proven, fp32 p1) ----------------
__global__ __launch_bounds__(256) void k_gat128(const float* __restrict__ q,
                                                const float* __restrict__ p,
                                                const float* __restrict__ avec,
                                                const float* __restrict__ badd,
                                                __nv_bfloat16* __restrict__ outh,
                                                __nv_bfloat16* __restrict__ outl) {
    int w = (blockIdx.x * blockDim.x + threadIdx.x) >> 5;
    int lane = threadIdx.x & 31;
    if (w >= N_NODES) return;
    int half = lane >> 4, hl = lane & 15;

    const float4* q4 = (const float4*)q;
    const float4* p4 = (const float4*)p;
    const float4* a4 = (const float4*)avec;
    float4 qv0 = q4[(size_t)w * 32 + hl * 2];
    float4 qv1 = q4[(size_t)w * 32 + hl * 2 + 1];
    float4 av0 = a4[hl * 2], av1 = a4[hl * 2 + 1];

    int beg = g_rowptr[w];
    int count = g_rowptr[w + 1] - beg;
    int n0 = (count + 1) >> 1;
    int base = beg + half * n0;
    int cnt_h = half ? (count - n0) : n0;

    float denom = 0.f;
    float s0 = 0.f, s1 = 0.f, s2 = 0.f, s3 = 0.f;
    float s4 = 0.f, s5 = 0.f, s6 = 0.f, s7 = 0.f;

    for (int it = 0; it < n0; it += 4) {
        bool act0 = it < cnt_h, act1 = it + 1 < cnt_h;
        bool act2 = it + 2 < cnt_h, act3 = it + 3 < cnt_h;
        int i0 = act0 ? g_csrc[base + it] : 0;
        int i1 = act1 ? g_csrc[base + it + 1] : 0;
        int i2 = act2 ? g_csrc[base + it + 2] : 0;
        int i3 = act3 ? g_csrc[base + it + 3] : 0;
        float4 pA0 = p4[(size_t)i0 * 32 + hl * 2];
        float4 pA1 = p4[(size_t)i0 * 32 + hl * 2 + 1];
        float4 pB0 = p4[(size_t)i1 * 32 + hl * 2];
        float4 pB1 = p4[(size_t)i1 * 32 + hl * 2 + 1];
        float4 pC0 = p4[(size_t)i2 * 32 + hl * 2];
        float4 pC1 = p4[(size_t)i2 * 32 + hl * 2 + 1];
        float4 pD0 = p4[(size_t)i3 * 32 + hl * 2];
        float4 pD1 = p4[(size_t)i3 * 32 + hl * 2 + 1];

        float pa = LRELU(qv0.x + pA0.x) * av0.x + LRELU(qv0.y + pA0.y) * av0.y +
                   LRELU(qv0.z + pA0.z) * av0.z + LRELU(qv0.w + pA0.w) * av0.w +
                   LRELU(qv1.x + pA1.x) * av1.x + LRELU(qv1.y + pA1.y) * av1.y +
                   LRELU(qv1.z + pA1.z) * av1.z + LRELU(qv1.w + pA1.w) * av1.w;
        float pb = LRELU(qv0.x + pB0.x) * av0.x + LRELU(qv0.y + pB0.y) * av0.y +
                   LRELU(qv0.z + pB0.z) * av0.z + LRELU(qv0.w + pB0.w) * av0.w +
                   LRELU(qv1.x + pB1.x) * av1.x + LRELU(qv1.y + pB1.y) * av1.y +
                   LRELU(qv1.z + pB1.z) * av1.z + LRELU(qv1.w + pB1.w) * av1.w;
        float pc = LRELU(qv0.x + pC0.x) * av0.x + LRELU(qv0.y + pC0.y) * av0.y +
                   LRELU(qv0.z + pC0.z) * av0.z + LRELU(qv0.w + pC0.w) * av0.w +
                   LRELU(qv1.x + pC1.x) * av1.x + LRELU(qv1.y + pC1.y) * av1.y +
                   LRELU(qv1.z + pC1.z) * av1.z + LRELU(qv1.w + pC1.w) * av1.w;
        float pd = LRELU(qv0.x + pD0.x) * av0.x + LRELU(qv0.y + pD0.y) * av0.y +
                   LRELU(qv0.z + pD0.z) * av0.z + LRELU(qv0.w + pD0.w) * av0.w +
                   LRELU(qv1.x + pD1.x) * av1.x + LRELU(qv1.y + pD1.y) * av1.y +
                   LRELU(qv1.z + pD1.z) * av1.z + LRELU(qv1.w + pD1.w) * av1.w;

#pragma unroll
        for (int o = 8; o; o >>= 1) {
            pa += __shfl_xor_sync(0xffffffffu, pa, o);
            pb += __shfl_xor_sync(0xffffffffu, pb, o);
            pc += __shfl_xor_sync(0xffffffffu, pc, o);
            pd += __shfl_xor_sync(0xffffffffu, pd, o);
        }
        float eA = act0 ? __expf(pa) : 0.f;
        float eB = act1 ? __expf(pb) : 0.f;
        float eC = act2 ? __expf(pc) : 0.f;
        float eD = act3 ? __expf(pd) : 0.f;
        denom += (eA + eB) + (eC + eD);
        s0 = fmaf(eA, pA0.x, fmaf(eB, pB0.x, fmaf(eC, pC0.x, fmaf(eD, pD0.x, s0))));
        s1 = fmaf(eA, pA0.y, fmaf(eB, pB0.y, fmaf(eC, pC0.y, fmaf(eD, pD0.y, s1))));
        s2 = fmaf(eA, pA0.z, fmaf(eB, pB0.z, fmaf(eC, pC0.z, fmaf(eD, pD0.z, s2))));
        s3 = fmaf(eA, pA0.w, fmaf(eB, pB0.w, fmaf(eC, pC0.w, fmaf(eD, pD0.w, s3))));
        s4 = fmaf(eA, pA1.x, fmaf(eB, pB1.x, fmaf(eC, pC1.x, fmaf(eD, pD1.x, s4))));
        s5 = fmaf(eA, pA1.y, fmaf(eB, pB1.y, fmaf(eC, pC1.y, fmaf(eD, pD1.y, s5))));
        s6 = fmaf(eA, pA1.z, fmaf(eB, pB1.z, fmaf(eC, pC1.z, fmaf(eD, pD1.z, s6))));
        s7 = fmaf(eA, pA1.w, fmaf(eB, pB1.w, fmaf(eC, pC1.w, fmaf(eD, pD1.w, s7))));
    }
    denom += __shfl_xor_sync(0xffffffffu, denom, 16);
    s0 += __shfl_xor_sync(0xffffffffu, s0, 16);
    s1 += __shfl_xor_sync(0xffffffffu, s1, 16);
    s2 += __shfl_xor_sync(0xffffffffu, s2, 16);
    s3 += __shfl_xor_sync(0xffffffffu, s3, 16);
    s4 += __shfl_xor_sync(0xffffffffu, s4, 16);
    s5 += __shfl_xor_sync(0xffffffffu, s5, 16);
    s6 += __shfl_xor_sync(0xffffffffu, s6, 16);
    s7 += __shfl_xor_sync(0xffffffffu, s7, 16);

    if (half == 0) {
        float inv = (count > 0) ? 1.f / denom : 0.f;
        int col = hl * 8;
        float v0 = gelu_erf(fmaf(s0, inv, badd[col + 0]));
        float v1 = gelu_erf(fmaf(s1, inv, badd[col + 1]));
        float v2 = gelu_erf(fmaf(s2, inv, badd[col + 2]));
        float v3 = gelu_erf(fmaf(s3, inv, badd[col + 3]));
        float v4 = gelu_erf(fmaf(s4, inv, badd[col + 4]));
        float v5 = gelu_erf(fmaf(s5, inv, badd[col + 5]));
        float v6 = gelu_erf(fmaf(s6, inv, badd[col + 6]));
        float v7 = gelu_erf(fmaf(s7, inv, badd[col + 7]));
        uint32_t h01, l01, h23, l23, h45, l45, h67, l67;
        split2(v0, v1, h01, l01);
        split2(v2, v3, h23, l23);
        split2(v4, v5, h45, l45);
        split2(v6, v7, h67, l67);
        *(uint4*)(outh + (size_t)w * 128 + col) = make_uint4(h01, h23, h45, h67);
        *(uint4*)(outl + (size_t)w * 128 + col) = make_uint4(l01, l23, l45, l67);
    }
}

// ---------------- GAT D=64 (R10 proven) ----------------
__global__ __launch_bounds__(256) void k_gat64(const float* __restrict__ q,
                                               const float* __restrict__ p,
                                               const float* __restrict__ avec,
                                               const float* __restrict__ bout,
                                               float* __restrict__ out) {
    int w = (blockIdx.x * blockDim.x + threadIdx.x) >> 5;
    int lane = threadIdx.x & 31;
    if (w >= N_NODES) return;
    int half = lane >> 4, hl = lane & 15;

    const float4* q4 = (const float4*)q;
    const float4* p4 = (const float4*)p;
    float4 qv = q4[(size_t)w * 16 + hl];
    float4 av = ((const float4*)avec)[hl];

    int beg = g_rowptr[w];
    int count = g_rowptr[w + 1] - beg;
    int n0 = (count + 1) >> 1;
    int base = beg + half * n0;
    int cnt_h = half ? (count - n0) : n0;

    float denom = 0.f;
    float s0 = 0.f, s1 = 0.f, s2 = 0.f, s3 = 0.f;

    for (int it = 0; it < n0; it += 4) {
        bool act0 = it < cnt_h, act1 = it + 1 < cnt_h;
        bool act2 = it + 2 < cnt_h, act3 = it + 3 < cnt_h;
        int i0 = act0 ? g_csrc[base + it] : 0;
        int i1 = act1 ? g_csrc[base + it + 1] : 0;
        int i2 = act2 ? g_csrc[base + it + 2] : 0;
        int i3 = act3 ? g_csrc[base + it + 3] : 0;
        float4 pA = p4[(size_t)i0 * 16 + hl];
        float4 pB = p4[(size_t)i1 * 16 + hl];
        float4 pC = p4[(size_t)i2 * 16 + hl];
        float4 pD = p4[(size_t)i3 * 16 + hl];

        float pa = LRELU(qv.x + pA.x) * av.x + LRELU(qv.y + pA.y) * av.y +
                   LRELU(qv.z + pA.z) * av.z + LRELU(qv.w + pA.w) * av.w;
        float pb = LRELU(qv.x + pB.x) * av.x + LRELU(qv.y + pB.y) * av.y +
                   LRELU(qv.z + pB.z) * av.z + LRELU(qv.w + pB.w) * av.w;
        float pc = LRELU(qv.x + pC.x) * av.x + LRELU(qv.y + pC.y) * av.y +
                   LRELU(qv.z + pC.z) * av.z + LRELU(qv.w + pC.w) * av.w;
        float pd = LRELU(qv.x + pD.x) * av.x + LRELU(qv.y + pD.y) * av.y +
                   LRELU(qv.z + pD.z) * av.z + LRELU(qv.w + pD.w) * av.w;

#pragma unroll
        for (int o = 8; o; o >>= 1) {
            pa += __shfl_xor_sync(0xffffffffu, pa, o);
            pb += __shfl_xor_sync(0xffffffffu, pb, o);
            pc += __shfl_xor_sync(0xffffffffu, pc, o);
            pd += __shfl_xor_sync(0xffffffffu, pd, o);
        }
        float eA = act0 ? __expf(pa) : 0.f;
        float eB = act1 ? __expf(pb) : 0.f;
        float eC = act2 ? __expf(pc) : 0.f;
        float eD = act3 ? __expf(pd) : 0.f;
        denom += (eA + eB) + (eC + eD);
        s0 = fmaf(eA, pA.x, fmaf(eB, pB.x, fmaf(eC, pC.x, fmaf(eD, pD.x, s0))));
        s1 = fmaf(eA, pA.y, fmaf(eB, pB.y, fmaf(eC, pC.y, fmaf(eD, pD.y, s1))));
        s2 = fmaf(eA, pA.z, fmaf(eB, pB.z, fmaf(eC, pC.z, fmaf(eD, pD.z, s2))));
        s3 = fmaf(eA, pA.w, fmaf(eB, pB.w, fmaf(eC, pC.w, fmaf(eD, pD.w, s3))));
    }
    denom += __shfl_xor_sync(0xffffffffu, denom, 16);
    s0 += __shfl_xor_sync(0xffffffffu, s0, 16);
    s1 += __shfl_xor_sync(0xffffffffu, s1, 16);
    s2 += __shfl_xor_sync(0xffffffffu, s2, 16);
    s3 += __shfl_xor_sync(0xffffffffu, s3, 16);

    if (half == 0) {
        float inv = (count > 0) ? 1.f / denom : 0.f;
        int col = hl * 4;
        float4 o;
        o.x = fmaf(s0, inv, bout[col + 0]);
        o.y = fmaf(s1, inv, bout[col + 1]);
        o.z = fmaf(s2, inv, bout[col + 2]);
        o.w = fmaf(s3, inv, bout[col + 3]);
        ((float4*)out)[(size_t)w * 16 + hl] = o;
    }
}

// ---------------- launch (R10 schedule) ----------------
extern "C" void kernel_launch(void* const* d_in, const int* in_sizes, int n_in,
                              void* d_out, int out_size) {
    const float* x    = (const float*)d_in[0];
    const float* W0   = (const float*)d_in[1];
    const float* b0   = (const float*)d_in[2];
    const float* Wq1  = (const float*)d_in[3];
    const float* bq1  = (const float*)d_in[4];
    const float* Wp1  = (const float*)d_in[5];
    const float* bp1  = (const float*)d_in[6];
    const float* a1   = (const float*)d_in[7];
    const float* bg2  = (const float*)d_in[8];
    const float* Wq2  = (const float*)d_in[9];
    const float* bq2  = (const float*)d_in[10];
    const float* Wp2  = (const float*)d_in[11];
    const float* bp2  = (const float*)d_in[12];
    const float* a2   = (const float*)d_in[13];
    const float* b_out= (const float*)d_in[14];
    const int*   src  = (const int*)d_in[15];
    const int*   dst  = (const int*)d_in[16];

    float *q1, *p1, *q2, *p2;
    cudaGetSymbolAddress((void**)&q1, g_q1);
    cudaGetSymbolAddress((void**)&p1, g_p1);
    cudaGetSymbolAddress((void**)&q2, g_q2);
    cudaGetSymbolAddress((void**)&p2, g_p2);

    __nv_bfloat16 *xh, *m1b, *m2h, *m2l;
    cudaGetSymbolAddress((void**)&xh, g_xh);
    cudaGetSymbolAddress((void**)&m1b, g_m1b);
    cudaGetSymbolAddress((void**)&m2h, g_m2h);
    cudaGetSymbolAddress((void**)&m2l, g_m2l);

    __nv_bfloat16 *w0h, *w0l, *wq1h, *wq1l, *wp1h, *wp1l, *wq2h, *wq2l, *wp2h, *wp2l;
    cudaGetSymbolAddress((void**)&w0h, g_w0h);
    cudaGetSymbolAddress((void**)&w0l, g_w0l);
    cudaGetSymbolAddress((void**)&wq1h, g_wq1h);
    cudaGetSymbolAddress((void**)&wq1l, g_wq1l);
    cudaGetSymbolAddress((void**)&wp1h, g_wp1h);
    cudaGetSymbolAddress((void**)&wp1l, g_wp1l);
    cudaGetSymbolAddress((void**)&wq2h, g_wq2h);
    cudaGetSymbolAddress((void**)&wq2l, g_wq2l);
    cudaGetSymbolAddress((void**)&wp2h, g_wp2h);
    cudaGetSymbolAddress((void**)&wp2l, g_wp2l);

    int* cntp;
    cudaGetSymbolAddress((void**)&cntp, g_cnt);

    const int gemm_gx = (N_NODES + 127) / 128;  // 391
    const dim3 qp_grid(gemm_gx, 2);
    const int gat_grid = (N_NODES + 7) / 8;     // 6250
    const int e4_grid = (N_EDGES / 4 + 255) / 256;

    // side stream for CSR build (overlaps with prep + layer-1 GEMMs)
    cudaStream_t s2;
    cudaStreamCreateWithFlags(&s2, cudaStreamNonBlocking);
    cudaEvent_t eFork, eJoin;
    cudaEventCreateWithFlags(&eFork, cudaEventDisableTiming);
    cudaEventCreateWithFlags(&eJoin, cudaEventDisableTiming);

    cudaEventRecord(eFork, 0);
    cudaStreamWaitEvent(s2, eFork, 0);

    cudaMemsetAsync(cntp, 0, N_NODES * sizeof(int), s2);
    k_hist<<<e4_grid, 256, 0, s2>>>(dst);
    k_scan_part<<<SCAN_BLOCKS, 256, 0, s2>>>();
    k_scan_mid<<<1, 256, 0, s2>>>();
    k_scan_final<<<SCAN_BLOCKS, 256, 0, s2>>>();
    k_scatter<<<e4_grid, 256, 0, s2>>>(src, dst);
    cudaEventRecord(eJoin, s2);

    // main chain
    k_prep_all<<<(XN / 4 + 16384 + 255) / 256, 256>>>(
        (const float4*)x, (const float4*)W0, (const float4*)Wq1,
        (const float4*)Wp1, (const float4*)Wq2, (const float4*)Wp2);
    // gemm1: 2-split, bf16 output m1b
    k_gemm2s<128, true, true><<<gemm_gx, 256>>>(
        xh, w0h, w0l, b0, nullptr, m1b,
        w0h, w0l, b0, nullptr, N_NODES);
    // qp1: 2-split from m1b, fp32 q1/p1
    k_gemm2s<128, false, false><<<qp_grid, 256>>>(
        m1b, wq1h, wq1l, bq1, q1, nullptr,
        wp1h, wp1l, bp1, p1, N_NODES);

    cudaStreamWaitEvent(0, eJoin, 0);
    k_gat128<<<gat_grid, 256>>>(q1, p1, a1, bg2, m2h, m2l);

    // gemm2: 3-split (output-critical)
    k_gemm3s<64><<<qp_grid, 256>>>(
        m2h, m2l, wq2h, wq2l, bq2, q2,
        wp2h, wp2l, bp2, p2, N_NODES);
    k_gat64<<<gat_grid, 256>>>(q2, p2, a2, b_out, (float*)d_out);

    cudaEventDestroy(eFork);
    cudaEventDestroy(eJoin);
    cudaStreamDestroy(s2);
}